// round 2
// baseline (speedup 1.0000x reference)
#include <cuda_runtime.h>
#include <cuda_bf16.h>

#define NUM_CLASSES 10
#define NSLOT 11            // 10 real classes + 1 dummy slot for mask==0
#define THREADS 256
#define BLOCKS (148 * 8)    // one full wave at 8 CTAs/SM

// Global scratch (allocation-free rule: __device__ globals)
__device__ float g_sum[NUM_CLASSES];
__device__ float g_cnt[NUM_CLASSES];

__global__ void zero_kernel() {
    int i = threadIdx.x;
    if (i < NUM_CLASSES) {
        g_sum[i] = 0.0f;
        g_cnt[i] = 0.0f;
    }
}

__device__ __forceinline__ void accum_one(float2* acc, int tid, float o, float t, int m) {
    float d = o - t;
    int c = __float2int_rz(t);          // targets are exact small ints
    int idx = (m == 1) ? c : NUM_CLASSES;  // invalid -> dummy slot
    float2* p = acc + idx * THREADS + tid; // bank = tid%32 -> conflict-free
    float2 v = *p;
    v.x = fmaf(d, d, v.x);              // sum of squared error
    v.y += 1.0f;                        // count (dummy slot absorbs invalid)
    *p = v;
}

__global__ __launch_bounds__(THREADS, 8)
void loss_main_kernel(const float4* __restrict__ o4,
                      const float4* __restrict__ t4,
                      const int4*   __restrict__ m4,
                      int nvec, int n) {
    __shared__ float2 acc[NSLOT * THREADS];   // 22528 B

    const int tid = threadIdx.x;

    // zero private accumulators
    #pragma unroll
    for (int c = 0; c < NSLOT; c++)
        acc[c * THREADS + tid] = make_float2(0.0f, 0.0f);
    __syncthreads();

    const int gtid   = blockIdx.x * THREADS + tid;
    const int stride = gridDim.x * THREADS;

    for (int i = gtid; i < nvec; i += stride) {
        float4 ov = o4[i];
        float4 tv = t4[i];
        int4   mv = m4[i];
        accum_one(acc, tid, ov.x, tv.x, mv.x);
        accum_one(acc, tid, ov.y, tv.y, mv.y);
        accum_one(acc, tid, ov.z, tv.z, mv.z);
        accum_one(acc, tid, ov.w, tv.w, mv.w);
    }

    // scalar tail (n % 4), if any
    const float* o1 = (const float*)o4;
    const float* t1 = (const float*)t4;
    const int*   m1 = (const int*)m4;
    for (int i = nvec * 4 + gtid; i < n; i += stride)
        accum_one(acc, tid, o1[i], t1[i], m1[i]);

    __syncthreads();

    // block reduction over the 256 thread-private columns (classes 0..9 only)
    for (int s = THREADS / 2; s > 0; s >>= 1) {
        if (tid < s) {
            #pragma unroll
            for (int c = 0; c < NUM_CLASSES; c++) {
                float2 a = acc[c * THREADS + tid];
                float2 b = acc[c * THREADS + tid + s];
                acc[c * THREADS + tid] = make_float2(a.x + b.x, a.y + b.y);
            }
        }
        __syncthreads();
    }

    if (tid < NUM_CLASSES) {
        float2 v = acc[tid * THREADS];
        atomicAdd(&g_sum[tid], v.x);
        atomicAdd(&g_cnt[tid], v.y);
    }
}

__global__ void finalize_kernel(float* __restrict__ out) {
    if (threadIdx.x == 0) {
        float loss = 0.0f;
        #pragma unroll
        for (int c = 0; c < NUM_CLASSES; c++) {
            float n = g_cnt[c];
            float s = g_sum[c];
            float le = (n > 0.0f) ? (s / fmaxf(n, 1.0f)) : 0.0f;
            out[1 + c] = le;                    // loss_each
            out[1 + NUM_CLASSES + c] = n;       // class_n
            loss = fmaf(0.1f, le, loss);        // WEIGHT = 0.1 each
        }
        out[0] = loss;
    }
}

extern "C" void kernel_launch(void* const* d_in, const int* in_sizes, int n_in,
                              void* d_out, int out_size) {
    const float* outputs = (const float*)d_in[0];
    const float* targets = (const float*)d_in[1];
    const int*   mask    = (const int*)d_in[2];
    int n    = in_sizes[0];
    int nvec = n / 4;

    zero_kernel<<<1, 32>>>();
    loss_main_kernel<<<BLOCKS, THREADS>>>((const float4*)outputs,
                                          (const float4*)targets,
                                          (const int4*)mask, nvec, n);
    finalize_kernel<<<1, 32>>>((float*)d_out);
}

// round 7
// speedup vs baseline: 1.0968x; 1.0968x over previous
#include <cuda_runtime.h>
#include <cuda_bf16.h>

#define NUM_CLASSES 10
#define NSLOT 11            // 10 real classes + 1 dummy slot for mask==0
#define THREADS 256
#define BLOCKS (148 * 8)    // one full wave at 8 CTAs/SM

// Global scratch (allocation-free rule: __device__ globals).
// Zero-initialized at module load; every launch leaves them zeroed again
// (last block resets after finalize), so replays are deterministic.
__device__ float        g_sum[NUM_CLASSES];
__device__ float        g_cnt[NUM_CLASSES];
__device__ unsigned int g_ticket;

__device__ __forceinline__ void accum_one(float2* acc, int tid, float o, float t, int m) {
    float d = o - t;
    int c = __float2int_rz(t);             // targets are exact small ints
    int idx = (m == 1) ? c : NUM_CLASSES;  // invalid -> dummy slot
    float2* p = acc + idx * THREADS + tid; // per-thread column -> conflict-free
    float2 v = *p;
    v.x = fmaf(d, d, v.x);                 // sum of squared error
    v.y += 1.0f;                           // count (dummy slot absorbs invalid)
    *p = v;
}

__global__ __launch_bounds__(THREADS, 8)
void loss_fused_kernel(const float4* __restrict__ o4,
                       const float4* __restrict__ t4,
                       const int4*   __restrict__ m4,
                       int nvec, int n,
                       float* __restrict__ out) {
    __shared__ float2 acc[NSLOT * THREADS];   // 22528 B
    __shared__ bool   s_is_last;

    const int tid = threadIdx.x;

    // zero private accumulators
    #pragma unroll
    for (int c = 0; c < NSLOT; c++)
        acc[c * THREADS + tid] = make_float2(0.0f, 0.0f);
    __syncthreads();

    const int gtid   = blockIdx.x * THREADS + tid;
    const int stride = gridDim.x * THREADS;

    for (int i = gtid; i < nvec; i += stride) {
        float4 ov = __ldcs(&o4[i]);        // streaming: read-once data
        float4 tv = __ldcs(&t4[i]);
        int4   mv = __ldcs(&m4[i]);
        accum_one(acc, tid, ov.x, tv.x, mv.x);
        accum_one(acc, tid, ov.y, tv.y, mv.y);
        accum_one(acc, tid, ov.z, tv.z, mv.z);
        accum_one(acc, tid, ov.w, tv.w, mv.w);
    }

    // scalar tail (n % 4), if any
    const float* o1 = (const float*)o4;
    const float* t1 = (const float*)t4;
    const int*   m1 = (const int*)m4;
    for (int i = nvec * 4 + gtid; i < n; i += stride)
        accum_one(acc, tid, o1[i], t1[i], m1[i]);

    __syncthreads();

    // block reduction over the 256 thread-private columns (classes 0..9 only)
    for (int s = THREADS / 2; s > 0; s >>= 1) {
        if (tid < s) {
            #pragma unroll
            for (int c = 0; c < NUM_CLASSES; c++) {
                float2 a = acc[c * THREADS + tid];
                float2 b = acc[c * THREADS + tid + s];
                acc[c * THREADS + tid] = make_float2(a.x + b.x, a.y + b.y);
            }
        }
        __syncthreads();
    }

    // per-block partial -> global accumulators
    if (tid < NUM_CLASSES) {
        float2 v = acc[tid * THREADS];
        atomicAdd(&g_sum[tid], v.x);
        atomicAdd(&g_cnt[tid], v.y);
        __threadfence();                    // order my REDs before block ticket
    }
    __syncthreads();

    // last-arriving block finalizes and resets scratch for the next replay
    if (tid == 0) {
        unsigned int t = atomicAdd(&g_ticket, 1u);
        s_is_last = (t == (unsigned int)gridDim.x - 1u);
    }
    __syncthreads();

    if (s_is_last && tid == 0) {
        __threadfence();
        float loss = 0.0f;
        #pragma unroll
        for (int c = 0; c < NUM_CLASSES; c++) {
            float s  = atomicAdd(&g_sum[c], 0.0f);   // coherent L2 read
            float nn = atomicAdd(&g_cnt[c], 0.0f);
            float le = (nn > 0.0f) ? (s / fmaxf(nn, 1.0f)) : 0.0f;
            out[1 + c] = le;                  // loss_each
            out[1 + NUM_CLASSES + c] = nn;    // class_n
            loss = fmaf(0.1f, le, loss);      // WEIGHT = 0.1 each
            g_sum[c] = 0.0f;                  // reset for next replay
            g_cnt[c] = 0.0f;
        }
        out[0] = loss;
        g_ticket = 0u;
    }
}

extern "C" void kernel_launch(void* const* d_in, const int* in_sizes, int n_in,
                              void* d_out, int out_size) {
    const float* outputs = (const float*)d_in[0];
    const float* targets = (const float*)d_in[1];
    const int*   mask    = (const int*)d_in[2];
    int n    = in_sizes[0];
    int nvec = n / 4;

    loss_fused_kernel<<<BLOCKS, THREADS>>>((const float4*)outputs,
                                           (const float4*)targets,
                                           (const int4*)mask, nvec, n,
                                           (float*)d_out);
}